// round 4
// baseline (speedup 1.0000x reference)
#include <cuda_runtime.h>
#include <cstdint>

#define BB 32
#define AA 8400
#define A4 2100
#define NCLS 80
#define KK 1024
#define GG 32
#define NSUP 16
#define MAXDET 300

// only decode outputs remain in global scratch
__device__ __align__(16) float g_conf[BB * AA];
__device__ __align__(16) int   g_cls[BB * AA];

// IEEE-exact IoU matching jnp order: inter / ((area_a + area_b) - inter + 1e-9)
__device__ __forceinline__ float iou_rn(float4 A_, float4 B_) {
    float ltx = fmaxf(A_.x, B_.x), lty = fmaxf(A_.y, B_.y);
    float rbx = fminf(A_.z, B_.z), rby = fminf(A_.w, B_.w);
    float w = fmaxf(__fsub_rn(rbx, ltx), 0.0f);
    float h = fmaxf(__fsub_rn(rby, lty), 0.0f);
    float inter = __fmul_rn(w, h);
    float aa = __fmul_rn(__fsub_rn(A_.z, A_.x), __fsub_rn(A_.w, A_.y));
    float ab = __fmul_rn(__fsub_rn(B_.z, B_.x), __fsub_rn(B_.w, B_.y));
    float den = __fadd_rn(__fsub_rn(__fadd_rn(aa, ab), inter), 1e-9f);
    return __fdiv_rn(inter, den);
}

// -------- K1: decode conf/cls, 4 anchors per thread (float4) --------
__global__ void k_decode(const float* __restrict__ preds) {
    int t = blockIdx.x * 256 + threadIdx.x;
    int b = blockIdx.y;
    if (t >= A4) return;
    const float4* p = (const float4*)(preds + (size_t)b * 84 * AA);
    float4 best = p[4 * A4 + t];
    int bx = 0, by = 0, bz = 0, bw = 0;
#pragma unroll 8
    for (int c = 1; c < NCLS; c++) {
        float4 s = p[(4 + c) * A4 + t];
        if (s.x > best.x) { best.x = s.x; bx = c; }
        if (s.y > best.y) { best.y = s.y; by = c; }
        if (s.z > best.z) { best.z = s.z; bz = c; }
        if (s.w > best.w) { best.w = s.w; bw = c; }
    }
    best.x = (best.x > 0.25f) ? best.x : 0.0f;
    best.y = (best.y > 0.25f) ? best.y : 0.0f;
    best.z = (best.z > 0.25f) ? best.z : 0.0f;
    best.w = (best.w > 0.25f) ? best.w : 0.0f;
    ((float4*)g_conf)[b * A4 + t] = best;
    ((int4*)g_cls)[b * A4 + t] = make_int4(bx, by, bz, bw);
}

// dynamic smem layout (bytes)
#define OFF_MASK 0                      // 1024*32 u32 = 131072
#define OFF_SBOX 131072                 // 1024 float4 = 16384
#define OFF_SA   147456                 // 1024 f32 = 4096
#define OFF_CONF 151552                 // 1024 f32 = 4096
#define OFF_CLS  155648                 // 1024 i32 = 4096
#define OFF_BOXM 159744                 // 1024 float4 = 16384
#define SMEM_TOTAL 176128
// after NMS scan, mask region is reused for compacted match arrays:
#define OFF_CBOX 0                      // 1024 float4
#define OFF_CCLS 16384                  // 1024 i32
#define OFF_CIDX 20480                  // 1024 i32

// -------- K2: fused select + mask + NMS + match (one block per image) --------
__global__ __launch_bounds__(1024, 1) void k_mega(const float* __restrict__ preds,
                                                  const float* __restrict__ gt_b,
                                                  const int* __restrict__ gt_c,
                                                  const unsigned* __restrict__ gt_m,
                                                  const int* __restrict__ c2s,
                                                  float* __restrict__ out) {
    extern __shared__ char smem[];
    unsigned* msk  = (unsigned*)(smem + OFF_MASK);
    float4*   sbx  = (float4*)(smem + OFF_SBOX);
    float*    sa   = (float*)(smem + OFF_SA);
    float*    sconf= (float*)(smem + OFF_CONF);
    int*      scls = (int*)(smem + OFF_CLS);
    float4*   sbm  = (float4*)(smem + OFF_BOXM);
    float4*   cbox = (float4*)(smem + OFF_CBOX);
    int*      ccls = (int*)(smem + OFF_CCLS);
    int*      cidx = (int*)(smem + OFF_CIDX);

    __shared__ unsigned long long ss[KK];
    __shared__ int hist[256];
    __shared__ int s_cum[257];
    __shared__ int wsum[8];
    __shared__ unsigned long long sh_pref;
    __shared__ int sh_m;
    __shared__ int sh_cnt;
    __shared__ unsigned sval[32];
    __shared__ unsigned skeep[32];
    __shared__ int wtot[32];
    __shared__ int s_np;
    __shared__ float   sbv[GG];
    __shared__ int     sbi[GG];
    __shared__ float   scat[NCLS];
    __shared__ float   ssup[NSUP];
    __shared__ float4  sgt[GG];
    __shared__ int     sgc[GG];
    __shared__ int     sgm[GG];

    int b = blockIdx.x, tid = threadIdx.x, lane = tid & 31, warp = tid >> 5;

    // ---- phase 0: GT + misc init ----
    if (tid < NCLS) scat[tid] = 0.0f;
    if (tid >= NCLS && tid < NCLS + NSUP) ssup[tid - NCLS] = 0.0f;
    if (tid < GG) {
        const float* gb = gt_b + ((size_t)b * GG + tid) * 4;
        sgt[tid] = make_float4(gb[0], gb[1], gb[2], gb[3]);
        sgc[tid] = gt_c[b * GG + tid];
        sgm[tid] = (gt_m[b * GG + tid] != 0u) ? 1 : 0;
    }
    if (tid == 0) { sh_pref = 0ull; sh_m = KK; sh_cnt = 0; }
    if (tid == 256) s_cum[256] = 0;

    // ---- phase 1: radix select over distinct keys conf|~idx ----
    unsigned long long rk[9];
#pragma unroll
    for (int e0 = 0; e0 < 9; e0++) {
        int e = e0 * 1024 + tid;
        unsigned long long key = 0ull;
        if (e < AA) {
            unsigned cb = __float_as_uint(g_conf[b * AA + e]);
            key = ((unsigned long long)cb << 32) | (0xFFFFFFFFu - (unsigned)e);
        }
        rk[e0] = key;
    }
    __syncthreads();

    for (int p = 0; p < 8; p++) {
        if (tid < 256) hist[tid] = 0;
        __syncthreads();
        int shift = 56 - 8 * p;
        unsigned long long pref = sh_pref;
        int m = sh_m;
#pragma unroll
        for (int e0 = 0; e0 < 9; e0++) {
            int e = e0 * 1024 + tid;
            int digit = 256;
            if (e < AA) {
                unsigned long long key = rk[e0];
                bool match = (p == 0) || (((key ^ pref) >> (shift + 8)) == 0ull);
                if (match) digit = (int)((key >> shift) & 255ull);
            }
            unsigned mm = __match_any_sync(0xFFFFFFFFu, digit);
            if (digit < 256 && lane == (__ffs(mm) - 1)) atomicAdd(&hist[digit], __popc(mm));
        }
        __syncthreads();
        int h = 0;
        if (tid < 256) {
            h = hist[tid];
#pragma unroll
            for (int off = 1; off < 32; off <<= 1) {
                int n = __shfl_down_sync(0xFFFFFFFFu, h, off);
                if (lane + off < 32) h += n;
            }
            if (lane == 0) wsum[tid >> 5] = h;
        }
        __syncthreads();
        if (tid < 256) {
            int w = tid >> 5, add = 0;
#pragma unroll
            for (int w2 = 0; w2 < 8; w2++) if (w2 > w) add += wsum[w2];
            s_cum[tid] = h + add;
        }
        __syncthreads();
        if (tid < 256) {
            int cd = s_cum[tid], cn = s_cum[tid + 1];
            if (cd >= m && cn < m) {
                sh_pref = pref | ((unsigned long long)tid << shift);
                sh_m = m - cn;
            }
        }
        __syncthreads();
    }
    unsigned long long T = sh_pref;

    // warp-aggregated compaction
#pragma unroll
    for (int e0 = 0; e0 < 9; e0++) {
        int e = e0 * 1024 + tid;
        bool sel = (e < AA) && (rk[e0] >= T);
        unsigned bal = __ballot_sync(0xFFFFFFFFu, sel);
        if (bal) {
            int basep = 0;
            if (lane == 0) basep = atomicAdd(&sh_cnt, __popc(bal));
            basep = __shfl_sync(0xFFFFFFFFu, basep, 0);
            if (sel) ss[basep + __popc(bal & ((1u << lane) - 1u))] = rk[e0];
        }
    }
    __syncthreads();

    // ---- phase 2: hybrid bitonic sort descending ----
    unsigned long long val = ss[tid];
    for (int k = 2; k <= KK; k <<= 1) {
        for (int j = k >> 1; j >= 32; j >>= 1) {
            __syncthreads();
            ss[tid] = val;
            __syncthreads();
            unsigned long long other = ss[tid ^ j];
            bool lower = (tid & j) == 0, desc = (tid & k) == 0;
            unsigned long long mx = val > other ? val : other;
            unsigned long long mn = val > other ? other : val;
            val = (lower == desc) ? mx : mn;
        }
        for (int j = ((k >> 1) < 32 ? (k >> 1) : 16); j >= 1; j >>= 1) {
            unsigned long long other = __shfl_xor_sync(0xFFFFFFFFu, val, j);
            bool lower = (tid & j) == 0, desc = (tid & k) == 0;
            unsigned long long mx = val > other ? val : other;
            unsigned long long mn = val > other ? other : val;
            val = (lower == desc) ? mx : mn;
        }
    }

    // ---- phase 3: epilogue -> smem tables ----
    {
        float conf = __uint_as_float((unsigned)(val >> 32));
        unsigned a = 0xFFFFFFFFu - (unsigned)(val & 0xFFFFFFFFull);
        int cls = g_cls[b * AA + a];
        const float* p = preds + (size_t)b * 84 * AA;
        float cx = p[a], cy = p[AA + a], w = p[2 * AA + a], h = p[3 * AA + a];
        float hw = __fmul_rn(w, 0.5f), hh = __fmul_rn(h, 0.5f);
        float x1 = __fsub_rn(cx, hw), y1 = __fsub_rn(cy, hh);
        float x2 = __fadd_rn(cx, hw), y2 = __fadd_rn(cy, hh);
        float sft = __fmul_rn((float)cls, 7680.0f);
        sconf[tid] = conf;
        scls[tid] = cls;
        sbm[tid] = make_float4(x1, y1, x2, y2);
        float4 sb = make_float4(__fadd_rn(x1, sft), __fadd_rn(y1, sft),
                                __fadd_rn(x2, sft), __fadd_rn(y2, sft));
        sbx[tid] = sb;
        sa[tid] = __fmul_rn(__fsub_rn(sb.z, sb.x), __fsub_rn(sb.w, sb.y));
        unsigned bal = __ballot_sync(0xFFFFFFFFu, conf > 0.0f);
        if (lane == 0) sval[warp] = bal;
    }
    __syncthreads();

    // ---- phase 4: suppression bitmask into smem ----
#pragma unroll
    for (int q = 0; q < 32; q++) {
        int word = q * 1024 + tid;          // linear (i, w)
        int i = word >> 5, w = word & 31;
        unsigned bits = 0u;
        if (w * 32 < i) {
            float4 bi = sbx[i];
            float ai = sa[i];
            int jmax = min(32, i - w * 32);
            for (int jj = 0; jj < jmax; jj++) {
                int j = w * 32 + jj;
                float4 bj = sbx[j];
                float ltx = fmaxf(bi.x, bj.x), lty = fmaxf(bi.y, bj.y);
                float rbx = fminf(bi.z, bj.z), rby = fminf(bi.w, bj.w);
                float wd = fmaxf(__fsub_rn(rbx, ltx), 0.0f);
                float ht = fmaxf(__fsub_rn(rby, lty), 0.0f);
                float inter = __fmul_rn(wd, ht);
                if (inter > 0.0f) {
                    float den = __fadd_rn(__fsub_rn(__fadd_rn(ai, sa[j]), inter), 1e-9f);
                    if (__fdiv_rn(inter, den) > 0.45f) bits |= 1u << jj;
                }
            }
        }
        msk[word] = bits;
    }
    __syncthreads();

    // ---- phase 5: chunked greedy NMS scan (warp 0) ----
    if (warp == 0) {
        unsigned keepw = 0u, finw = 0u;
        int cnt = 0;
        for (int c = 0; c < 32; c++) {
            unsigned pre = 0u;
            const unsigned* base = msk + (c * 32) * 32 + lane;
            if (__any_sync(0xFFFFFFFFu, keepw != 0u)) {
#pragma unroll
                for (int i = 0; i < 32; i++)
                    if (base[i * 32] & keepw) pre |= 1u << i;
            }
            unsigned prevSup = __reduce_or_sync(0xFFFFFFFFu, pre);
            unsigned t_own = msk[(c * 32 + lane) * 32 + c];   // intra-chunk triangle row
            unsigned pend = sval[c] & ~prevSup;
            unsigned kc = 0u;
            while (pend) {
                int l = __ffs(pend) - 1;
                kc |= 1u << l;
                pend &= ~(1u << l);
                unsigned supb = __ballot_sync(0xFFFFFFFFu, (t_own >> l) & 1u);
                pend &= ~supb;
            }
            if (lane == c) {
                keepw = kc;
                unsigned f = 0u;
                int allowed = MAXDET - cnt;
                if (allowed > 0) {
                    if (__popc(kc) <= allowed) f = kc;
                    else {
                        unsigned tmp = kc;
                        for (int t2 = 0; t2 < allowed; t2++) { f |= tmp & (0u - tmp); tmp &= tmp - 1u; }
                    }
                }
                finw = f;
            }
            cnt += __popc(kc);
        }
        skeep[lane] = finw;
    }
    __syncthreads();

    // ---- phase 6: match — stable compaction (1 row/thread) ----
    bool pv;
    {
        float c = sconf[tid];
        pv = (((skeep[warp] >> lane) & 1u) != 0u) && (c > 0.5f);
    }
    unsigned bal = __ballot_sync(0xFFFFFFFFu, pv);
    if (lane == 0) wtot[warp] = __popc(bal);
    // snapshot row data before mask region is overwritten
    float4 myBox = sbm[tid];
    int    myCls = scls[tid];
    __syncthreads();
    int basew = 0;
#pragma unroll
    for (int w2 = 0; w2 < 32; w2++) if (w2 < warp) basew += wtot[w2];
    if (pv) {
        int pos = basew + __popc(bal & ((1u << lane) - 1u));
        cbox[pos] = myBox;
        ccls[pos] = myCls;
        cidx[pos] = tid;
    }
    if (tid == 0) {
        int s = 0;
#pragma unroll
        for (int w2 = 0; w2 < 32; w2++) s += wtot[w2];
        s_np = s;
    }
    __syncthreads();
    int n_pv = s_np;

    // ---- phase 7: warp g matches GT g over compacted list ----
    {
        int g = warp;
        float4 gb = sgt[g];
        int gc = sgc[g];
        float bv = -1.0f;
        int bi = 0;
        for (int j = lane; j < n_pv; j += 32) {
            if (ccls[j] == gc) {
                float v = iou_rn(cbox[j], gb);
                if (v > bv) { bv = v; bi = cidx[j]; }
            }
        }
#pragma unroll
        for (int off = 16; off; off >>= 1) {
            float ov = __shfl_down_sync(0xFFFFFFFFu, bv, off);
            int   oi = __shfl_down_sync(0xFFFFFFFFu, bi, off);
            if (ov > bv || (ov == bv && oi < bi)) { bv = ov; bi = oi; }
        }
        if (lane == 0) { sbv[g] = bv; sbi[g] = bi; }
    }
    __syncthreads();
    if (tid < GG) {
        float gm = (float)sgm[tid];
        atomicAdd(&scat[sgc[tid]], gm);
        atomicAdd(&ssup[c2s[sgc[tid]]], gm);
    }
    __syncthreads();
    if (tid == 0) {
        int n_gt = 0, n_hit = 0;
        float si = 0.0f, sc = 0.0f;
        for (int g = 0; g < GG; g++) {
            n_gt += sgm[g];
            bool hit = (sbv[g] > 0.6f) && (sgm[g] != 0);
            if (hit) { n_hit++; si = __fadd_rn(si, sbv[g]); sc = __fadd_rn(sc, sconf[sbi[g]]); }
        }
        float r0, r1, r2, r3, r4;
        if (n_gt == 0) {
            if (n_pv == 0) { r0 = 1.0f; r1 = 1.0f; r2 = -1.0f; r3 = -1.0f; r4 = 1.0f; }
            else           { r0 = 0.0f; r1 = 1.0f; r2 = -2.0f; r3 = -2.0f; r4 = 0.0f; }
        } else {
            float fh = (float)n_hit;
            r0 = __fdiv_rn(si, fmaxf(fh, 1.0f));
            r1 = (n_hit > 0) ? __fdiv_rn(sc, fmaxf(fh, 1.0f)) : 1.0f;
            float bc = -1.0f; int bci = 0;
            for (int c = 0; c < NCLS; c++) if (scat[c] > bc) { bc = scat[c]; bci = c; }
            r2 = (float)bci;
            float bs = -1.0f; int bsi = 0;
            for (int s = 0; s < NSUP; s++) if (ssup[s] > bs) { bs = ssup[s]; bsi = s; }
            r3 = (float)bsi;
            r4 = __fdiv_rn(fh, fmaxf((float)n_gt, 1.0f));
        }
        out[b * 5 + 0] = r0;
        out[b * 5 + 1] = r1;
        out[b * 5 + 2] = r2;
        out[b * 5 + 3] = r3;
        out[b * 5 + 4] = r4;
    }
}

extern "C" void kernel_launch(void* const* d_in, const int* in_sizes, int n_in,
                              void* d_out, int out_size) {
    const float*    preds = (const float*)d_in[0];
    const float*    gtb   = (const float*)d_in[1];
    const int*      gtc   = (const int*)d_in[2];
    const unsigned* gtm   = (const unsigned*)d_in[3];
    const int*      c2s   = (const int*)d_in[4];
    float* out = (float*)d_out;

    cudaFuncSetAttribute(k_mega, cudaFuncAttributeMaxDynamicSharedMemorySize, SMEM_TOTAL);

    dim3 g1((A4 + 255) / 256, BB);
    k_decode<<<g1, 256>>>(preds);
    k_mega<<<BB, 1024, SMEM_TOTAL>>>(preds, gtb, gtc, gtm, c2s, out);
}

// round 8
// speedup vs baseline: 3.0720x; 3.0720x over previous
#include <cuda_runtime.h>
#include <cstdint>

#define BB 32
#define AA 8400
#define A4 2100
#define NCLS 80
#define KK 1024
#define GG 32
#define NSUP 16
#define MAXDET 300

__device__ __align__(16) float g_conf[BB * AA];
__device__ __align__(16) int   g_cls[BB * AA];

__device__ __forceinline__ float iou_rn(float4 A_, float4 B_) {
    float ltx = fmaxf(A_.x, B_.x), lty = fmaxf(A_.y, B_.y);
    float rbx = fminf(A_.z, B_.z), rby = fminf(A_.w, B_.w);
    float w = fmaxf(__fsub_rn(rbx, ltx), 0.0f);
    float h = fmaxf(__fsub_rn(rby, lty), 0.0f);
    float inter = __fmul_rn(w, h);
    float aa = __fmul_rn(__fsub_rn(A_.z, A_.x), __fsub_rn(A_.w, A_.y));
    float ab = __fmul_rn(__fsub_rn(B_.z, B_.x), __fsub_rn(B_.w, B_.y));
    float den = __fadd_rn(__fsub_rn(__fadd_rn(aa, ab), inter), 1e-9f);
    return __fdiv_rn(inter, den);
}

// -------- K1: decode conf/cls, 4 anchors per thread (float4) --------
__global__ void k_decode(const float* __restrict__ preds) {
    int t = blockIdx.x * 256 + threadIdx.x;
    int b = blockIdx.y;
    if (t >= A4) return;
    const float4* p = (const float4*)(preds + (size_t)b * 84 * AA);
    float4 best = p[4 * A4 + t];
    int bx = 0, by = 0, bz = 0, bw = 0;
#pragma unroll 8
    for (int c = 1; c < NCLS; c++) {
        float4 s = p[(4 + c) * A4 + t];
        if (s.x > best.x) { best.x = s.x; bx = c; }
        if (s.y > best.y) { best.y = s.y; by = c; }
        if (s.z > best.z) { best.z = s.z; bz = c; }
        if (s.w > best.w) { best.w = s.w; bw = c; }
    }
    best.x = (best.x > 0.25f) ? best.x : 0.0f;
    best.y = (best.y > 0.25f) ? best.y : 0.0f;
    best.z = (best.z > 0.25f) ? best.z : 0.0f;
    best.w = (best.w > 0.25f) ? best.w : 0.0f;
    ((float4*)g_conf)[b * A4 + t] = best;
    ((int4*)g_cls)[b * A4 + t] = make_int4(bx, by, bz, bw);
}

// dynamic smem layout (bytes)
#define OFF_MASK 0                      // 1024*32 u32 = 131072
#define OFF_SBOX 131072                 // 1024 float4 = 16384
#define OFF_SA   147456                 // 1024 f32 = 4096
#define OFF_CONF 151552                 // 1024 f32
#define OFF_CLS  155648                 // 1024 i32
#define OFF_BOXM 159744                 // 1024 float4 = 16384
#define SMEM_TOTAL 176128
// after scan, mask region reused for compacted match arrays
#define OFF_CBOX 0
#define OFF_CCLS 16384
#define OFF_CIDX 20480

__global__ __launch_bounds__(1024, 1) void k_mega2(const float* __restrict__ preds,
                                                   const float* __restrict__ gt_b,
                                                   const int* __restrict__ gt_c,
                                                   const unsigned* __restrict__ gt_m,
                                                   const int* __restrict__ c2s,
                                                   float* __restrict__ out) {
    extern __shared__ char smem[];
    unsigned* msk  = (unsigned*)(smem + OFF_MASK);
    float4*   sbx  = (float4*)(smem + OFF_SBOX);
    float*    sa   = (float*)(smem + OFF_SA);
    float*    sconf= (float*)(smem + OFF_CONF);
    int*      scls = (int*)(smem + OFF_CLS);
    float4*   sbm  = (float4*)(smem + OFF_BOXM);
    float4*   cbox = (float4*)(smem + OFF_CBOX);
    int*      ccls = (int*)(smem + OFF_CCLS);
    int*      cidx = (int*)(smem + OFF_CIDX);

    __shared__ unsigned long long ss[KK];
    __shared__ int hist[256];
    __shared__ int s_cum[257];
    __shared__ int wsum[8];
    __shared__ int eqs[288];
    __shared__ int prefq[288];
    __shared__ int wsum9[9];
    __shared__ unsigned sh_pref;
    __shared__ int sh_m;
    __shared__ int sh_cnt;
    __shared__ unsigned sval[32];
    __shared__ unsigned skeep[32];
    __shared__ int wtot[32];
    __shared__ int s_np;
    __shared__ float   sbv[GG];
    __shared__ int     sbi[GG];
    __shared__ float   scat[NCLS];
    __shared__ float   ssup[NSUP];
    __shared__ float4  sgt[GG];
    __shared__ int     sgc[GG];
    __shared__ int     sgm[GG];

    int b = blockIdx.x, tid = threadIdx.x, lane = tid & 31, warp = tid >> 5;

    // ---- phase 0: GT + init ----
    if (tid < NCLS) scat[tid] = 0.0f;
    if (tid >= NCLS && tid < NCLS + NSUP) ssup[tid - NCLS] = 0.0f;
    if (tid < GG) {
        const float* gb = gt_b + ((size_t)b * GG + tid) * 4;
        sgt[tid] = make_float4(gb[0], gb[1], gb[2], gb[3]);
        sgc[tid] = gt_c[b * GG + tid];
        sgm[tid] = (gt_m[b * GG + tid] != 0u) ? 1 : 0;
    }
    if (tid == 0) { sh_pref = 0u; sh_m = KK; sh_cnt = 0; }
    if (tid == 256) s_cum[256] = 0;

    // ---- phase 1: 4-pass radix select on 32-bit conf bits ----
    unsigned rka[9];
#pragma unroll
    for (int e0 = 0; e0 < 9; e0++) {
        int e = e0 * 1024 + tid;
        rka[e0] = (e < AA) ? __float_as_uint(g_conf[b * AA + e]) : 0u;
    }
    __syncthreads();

    for (int p = 0; p < 4; p++) {
        if (tid < 256) hist[tid] = 0;
        __syncthreads();
        int shift = 24 - 8 * p;
        unsigned pref = sh_pref;
        int m = sh_m;
#pragma unroll
        for (int e0 = 0; e0 < 9; e0++) {
            int e = e0 * 1024 + tid;
            int digit = 256;
            if (e < AA) {
                unsigned key = rka[e0];
                bool match = (p == 0) || (((key ^ pref) >> (shift + 8)) == 0u);
                if (match) digit = (int)((key >> shift) & 255u);
            }
            unsigned mm = __match_any_sync(0xFFFFFFFFu, digit);
            if (digit < 256 && lane == (__ffs(mm) - 1)) atomicAdd(&hist[digit], __popc(mm));
        }
        __syncthreads();
        int h = 0;
        if (tid < 256) {
            h = hist[tid];
#pragma unroll
            for (int off = 1; off < 32; off <<= 1) {
                int n = __shfl_down_sync(0xFFFFFFFFu, h, off);
                if (lane + off < 32) h += n;
            }
            if (lane == 0) wsum[tid >> 5] = h;
        }
        __syncthreads();
        if (tid < 256) {
            int w = tid >> 5, add = 0;
#pragma unroll
            for (int w2 = 0; w2 < 8; w2++) if (w2 > w) add += wsum[w2];
            s_cum[tid] = h + add;
        }
        __syncthreads();
        if (tid < 256) {
            int cd = s_cum[tid], cn = s_cum[tid + 1];
            if (cd >= m && cn < m) {
                sh_pref = pref | ((unsigned)tid << shift);
                sh_m = m - cn;
            }
        }
        __syncthreads();
    }
    unsigned Tc = sh_pref;
    int m_tie = sh_m;

    // tie ranks: ordered (chunk, warp, lane) prefix over equal-conf elements
#pragma unroll
    for (int e0 = 0; e0 < 9; e0++) {
        int e = e0 * 1024 + tid;
        bool eq = (e < AA) && (rka[e0] == Tc);
        unsigned eb = __ballot_sync(0xFFFFFFFFu, eq);
        if (lane == 0) eqs[e0 * 32 + warp] = __popc(eb);
    }
    __syncthreads();
    if (tid < 288) {
        int v = eqs[tid];
        int incl = v;
#pragma unroll
        for (int off = 1; off < 32; off <<= 1) {
            int n = __shfl_up_sync(0xFFFFFFFFu, incl, off);
            if (lane >= off) incl += n;
        }
        if (lane == 31) wsum9[tid >> 5] = incl;
        prefq[tid] = incl - v;   // within-warp exclusive
    }
    __syncthreads();
    if (tid < 288) {
        int w9 = tid >> 5, add = 0;
#pragma unroll
        for (int k2 = 0; k2 < 9; k2++) if (k2 < w9) add += wsum9[k2];
        prefq[tid] += add;
    }
    __syncthreads();

    // selection + warp-aggregated compaction (64-bit sort keys built here)
#pragma unroll
    for (int e0 = 0; e0 < 9; e0++) {
        int e = e0 * 1024 + tid;
        unsigned kb = rka[e0];
        bool inb = (e < AA);
        bool eq = inb && (kb == Tc);
        unsigned eb = __ballot_sync(0xFFFFFFFFu, eq);
        int rank = prefq[e0 * 32 + warp] + __popc(eb & ((1u << lane) - 1u));
        bool sel = (inb && kb > Tc) || (eq && rank < m_tie);
        unsigned bal = __ballot_sync(0xFFFFFFFFu, sel);
        if (bal) {
            int basep = 0;
            if (lane == 0) basep = atomicAdd(&sh_cnt, __popc(bal));
            basep = __shfl_sync(0xFFFFFFFFu, basep, 0);
            if (sel) ss[basep + __popc(bal & ((1u << lane) - 1u))] =
                ((unsigned long long)kb << 32) | (0xFFFFFFFFu - (unsigned)e);
        }
    }
    __syncthreads();

    // ---- phase 2: hybrid bitonic sort descending ----
    unsigned long long val = ss[tid];
    for (int k = 2; k <= KK; k <<= 1) {
        for (int j = k >> 1; j >= 32; j >>= 1) {
            __syncthreads();
            ss[tid] = val;
            __syncthreads();
            unsigned long long other = ss[tid ^ j];
            bool lower = (tid & j) == 0, desc = (tid & k) == 0;
            unsigned long long mx = val > other ? val : other;
            unsigned long long mn = val > other ? other : val;
            val = (lower == desc) ? mx : mn;
        }
        for (int j = ((k >> 1) < 32 ? (k >> 1) : 16); j >= 1; j >>= 1) {
            unsigned long long other = __shfl_xor_sync(0xFFFFFFFFu, val, j);
            bool lower = (tid & j) == 0, desc = (tid & k) == 0;
            unsigned long long mx = val > other ? val : other;
            unsigned long long mn = val > other ? other : val;
            val = (lower == desc) ? mx : mn;
        }
    }

    // ---- phase 3: epilogue -> smem tables ----
    {
        float conf = __uint_as_float((unsigned)(val >> 32));
        unsigned a = 0xFFFFFFFFu - (unsigned)(val & 0xFFFFFFFFull);
        int cls = g_cls[b * AA + a];
        const float* p = preds + (size_t)b * 84 * AA;
        float cx = p[a], cy = p[AA + a], w = p[2 * AA + a], h = p[3 * AA + a];
        float hw = __fmul_rn(w, 0.5f), hh = __fmul_rn(h, 0.5f);
        float x1 = __fsub_rn(cx, hw), y1 = __fsub_rn(cy, hh);
        float x2 = __fadd_rn(cx, hw), y2 = __fadd_rn(cy, hh);
        float sft = __fmul_rn((float)cls, 7680.0f);
        sconf[tid] = conf;
        scls[tid] = cls;
        sbm[tid] = make_float4(x1, y1, x2, y2);
        float4 sb = make_float4(__fadd_rn(x1, sft), __fadd_rn(y1, sft),
                                __fadd_rn(x2, sft), __fadd_rn(y2, sft));
        sbx[tid] = sb;
        sa[tid] = __fmul_rn(__fsub_rn(sb.z, sb.x), __fsub_rn(sb.w, sb.y));
        unsigned bal = __ballot_sync(0xFFFFFFFFu, conf > 0.0f);
        if (lane == 0) sval[warp] = bal;
    }
    __syncthreads();

    // ---- phase 4: suppression mask via ballot tiles (conflict-free) ----
    for (int t = warp; t < 528; t += 32) {
        int I = (int)((sqrtf(8.0f * (float)t + 1.0f) - 1.0f) * 0.5f);
        while ((I + 1) * (I + 2) / 2 <= t) I++;
        while (I * (I + 1) / 2 > t) I--;
        int J = t - I * (I + 1) / 2;
        float4 bj = sbx[J * 32 + lane];
        float  aj = sa[J * 32 + lane];
        unsigned myword = 0u;
#pragma unroll
        for (int i = 0; i < 32; i++) {
            float4 bi = sbx[I * 32 + i];
            float  ai = sa[I * 32 + i];
            float ltx = fmaxf(bi.x, bj.x), lty = fmaxf(bi.y, bj.y);
            float rbx = fminf(bi.z, bj.z), rby = fminf(bi.w, bj.w);
            float wd = fmaxf(__fsub_rn(rbx, ltx), 0.0f);
            float ht = fmaxf(__fsub_rn(rby, lty), 0.0f);
            float inter = __fmul_rn(wd, ht);
            bool pq = false;
            if (inter > 0.0f) {
                float den = __fadd_rn(__fsub_rn(__fadd_rn(ai, aj), inter), 1e-9f);
                pq = __fdiv_rn(inter, den) > 0.45f;
            }
            unsigned bal = __ballot_sync(0xFFFFFFFFu, pq);
            if (lane == i) myword = bal;
        }
        if (I == J) myword &= (1u << lane) - 1u;   // strict lower triangle
        msk[(I * 32 + lane) * 32 + J] = myword;
    }
    __syncthreads();

    // ---- phase 5: chunked greedy NMS via closure rounds (warp 0) ----
    if (warp == 0) {
        unsigned keepw = 0u, finw = 0u;
        int cnt = 0;
        for (int c = 0; c < 32; c++) {
            unsigned pre = 0u;
            const unsigned* base = msk + (c * 32) * 32 + lane;
            if (__any_sync(0xFFFFFFFFu, keepw != 0u)) {
#pragma unroll
                for (int i = 0; i < 32; i++)
                    if (base[i * 32] & keepw) pre |= 1u << i;
            }
            unsigned prevSup = __reduce_or_sync(0xFFFFFFFFu, pre);
            unsigned t_own = msk[(c * 32 + lane) * 32 + c];
            unsigned pend = sval[c] & ~prevSup;
            unsigned kc = 0u;
            while (pend) {
                bool mine = ((pend >> lane) & 1u) && ((t_own & pend) == 0u);
                unsigned newK = __ballot_sync(0xFFFFFFFFu, mine);
                kc |= newK;
                unsigned supb = __ballot_sync(0xFFFFFFFFu, (t_own & newK) != 0u);
                pend &= ~(newK | supb);
            }
            if (lane == c) {
                keepw = kc;
                unsigned f = 0u;
                int allowed = MAXDET - cnt;
                if (allowed > 0) {
                    if (__popc(kc) <= allowed) f = kc;
                    else {
                        unsigned tmp = kc;
                        for (int t2 = 0; t2 < allowed; t2++) { f |= tmp & (0u - tmp); tmp &= tmp - 1u; }
                    }
                }
                finw = f;
            }
            cnt += __popc(kc);
        }
        skeep[lane] = finw;
    }
    __syncthreads();

    // ---- phase 6: stable compaction of passing preds (into msk region) ----
    bool pv;
    {
        float c = sconf[tid];
        pv = (((skeep[warp] >> lane) & 1u) != 0u) && (c > 0.5f);
    }
    unsigned bal6 = __ballot_sync(0xFFFFFFFFu, pv);
    if (lane == 0) wtot[warp] = __popc(bal6);
    float4 myBox = sbm[tid];
    int    myCls = scls[tid];
    __syncthreads();
    int basew = 0;
#pragma unroll
    for (int w2 = 0; w2 < 32; w2++) if (w2 < warp) basew += wtot[w2];
    if (pv) {
        int pos = basew + __popc(bal6 & ((1u << lane) - 1u));
        cbox[pos] = myBox;
        ccls[pos] = myCls;
        cidx[pos] = tid;
    }
    if (tid == 0) {
        int s = 0;
#pragma unroll
        for (int w2 = 0; w2 < 32; w2++) s += wtot[w2];
        s_np = s;
    }
    __syncthreads();
    int n_pv = s_np;

    // ---- phase 7: warp g matches GT g over compacted list ----
    {
        int g = warp;
        float4 gb = sgt[g];
        int gc = sgc[g];
        float bv = -1.0f;
        int bi = 0;
        for (int j = lane; j < n_pv; j += 32) {
            if (ccls[j] == gc) {
                float v = iou_rn(cbox[j], gb);
                if (v > bv) { bv = v; bi = cidx[j]; }
            }
        }
#pragma unroll
        for (int off = 16; off; off >>= 1) {
            float ov = __shfl_down_sync(0xFFFFFFFFu, bv, off);
            int   oi = __shfl_down_sync(0xFFFFFFFFu, bi, off);
            if (ov > bv || (ov == bv && oi < bi)) { bv = ov; bi = oi; }
        }
        if (lane == 0) { sbv[g] = bv; sbi[g] = bi; }
    }
    __syncthreads();
    if (tid < GG) {
        float gm = (float)sgm[tid];
        atomicAdd(&scat[sgc[tid]], gm);
        atomicAdd(&ssup[c2s[sgc[tid]]], gm);
    }
    __syncthreads();
    if (tid == 0) {
        int n_gt = 0, n_hit = 0;
        float si = 0.0f, sc = 0.0f;
        for (int g = 0; g < GG; g++) {
            n_gt += sgm[g];
            bool hit = (sbv[g] > 0.6f) && (sgm[g] != 0);
            if (hit) { n_hit++; si = __fadd_rn(si, sbv[g]); sc = __fadd_rn(sc, sconf[sbi[g]]); }
        }
        float r0, r1, r2, r3, r4;
        if (n_gt == 0) {
            if (n_pv == 0) { r0 = 1.0f; r1 = 1.0f; r2 = -1.0f; r3 = -1.0f; r4 = 1.0f; }
            else           { r0 = 0.0f; r1 = 1.0f; r2 = -2.0f; r3 = -2.0f; r4 = 0.0f; }
        } else {
            float fh = (float)n_hit;
            r0 = __fdiv_rn(si, fmaxf(fh, 1.0f));
            r1 = (n_hit > 0) ? __fdiv_rn(sc, fmaxf(fh, 1.0f)) : 1.0f;
            float bc = -1.0f; int bci = 0;
            for (int c = 0; c < NCLS; c++) if (scat[c] > bc) { bc = scat[c]; bci = c; }
            r2 = (float)bci;
            float bs = -1.0f; int bsi = 0;
            for (int s = 0; s < NSUP; s++) if (ssup[s] > bs) { bs = ssup[s]; bsi = s; }
            r3 = (float)bsi;
            r4 = __fdiv_rn(fh, fmaxf((float)n_gt, 1.0f));
        }
        out[b * 5 + 0] = r0;
        out[b * 5 + 1] = r1;
        out[b * 5 + 2] = r2;
        out[b * 5 + 3] = r3;
        out[b * 5 + 4] = r4;
    }
}

extern "C" void kernel_launch(void* const* d_in, const int* in_sizes, int n_in,
                              void* d_out, int out_size) {
    const float*    preds = (const float*)d_in[0];
    const float*    gtb   = (const float*)d_in[1];
    const int*      gtc   = (const int*)d_in[2];
    const unsigned* gtm   = (const unsigned*)d_in[3];
    const int*      c2s   = (const int*)d_in[4];
    float* out = (float*)d_out;

    cudaFuncSetAttribute(k_mega2, cudaFuncAttributeMaxDynamicSharedMemorySize, SMEM_TOTAL);

    dim3 g1((A4 + 255) / 256, BB);
    k_decode<<<g1, 256>>>(preds);
    k_mega2<<<BB, 1024, SMEM_TOTAL>>>(preds, gtb, gtc, gtm, c2s, out);
}